// round 2
// baseline (speedup 1.0000x reference)
#include <cuda_runtime.h>

// Problem shapes (fixed per reference setup_inputs)
#define BB  2
#define SS  2048
#define HH  4096
#define NHD 32
#define NSL 100
#define DD  64
#define BSR (BB*SS)       // 4096 total (b,s) rows

typedef unsigned long long ull;

// -------- scratch (no allocations allowed) --------
__device__ float g_gate[BSR];
__device__ float g_WqT[HH*DD];    // W_q transposed to [H][D]
__device__ float g_logrel[NSL];

// -------- packed f32x2 helpers --------
__device__ __forceinline__ ull pk2(float lo, float hi){
    ull r; asm("mov.b64 %0, {%1, %2};" : "=l"(r) : "f"(lo), "f"(hi)); return r;
}
__device__ __forceinline__ void upk2(ull v, float& lo, float& hi){
    asm("mov.b64 {%0, %1}, %2;" : "=f"(lo), "=f"(hi) : "l"(v));
}
__device__ __forceinline__ void fma2(ull& d, ull a, ull b){
    asm("fma.rn.f32x2 %0, %1, %2, %0;" : "+l"(d) : "l"(a), "l"(b));
}
union F4U { float4 f; ull u[2]; };

// ============================================================
// prep: transpose W_q [D,H] -> WqT [H,D]; log(reliability)
// ============================================================
__global__ void prep_kernel(const float* __restrict__ Wq,
                            const float* __restrict__ rel)
{
    int idx = blockIdx.x * blockDim.x + threadIdx.x;
    if (idx < HH*DD) {
        int h = idx >> 6, d = idx & 63;
        g_WqT[idx] = Wq[d*HH + h];
    }
    if (idx < NSL) g_logrel[idx] = __logf(rel[idx] + 1e-10f);
}

// ============================================================
// entropy: per (b,s) row, mean over 32 heads of paw[b,h,s,:],
// entropy, sigmoid gate + veto. 1.07 GB streamed -> DRAM bound.
// ============================================================
__global__ __launch_bounds__(256)
void entropy_kernel(const float* __restrict__ paw,
                    const float* __restrict__ w1p,
                    const float* __restrict__ bp)
{
    int bs = blockIdx.x;            // 0..4095
    int t  = threadIdx.x;           // 0..255
    size_t b = (size_t)(bs >> 11);
    size_t s = (size_t)(bs & 2047);
    const float* base = paw + ((b*NHD)*SS + s) * (size_t)SS;

    float4 a0 = make_float4(0.f,0.f,0.f,0.f);
    float4 a1 = make_float4(0.f,0.f,0.f,0.f);
    #pragma unroll 4
    for (int h = 0; h < NHD; ++h) {
        const float4* p = (const float4*)(base + (size_t)h * SS * SS);
        float4 x0 = p[t];
        float4 x1 = p[t + 256];
        a0.x += x0.x; a0.y += x0.y; a0.z += x0.z; a0.w += x0.w;
        a1.x += x1.x; a1.y += x1.y; a1.z += x1.z; a1.w += x1.w;
    }
    const float inv = 1.0f / 32.0f;
    float v[8] = {a0.x,a0.y,a0.z,a0.w,a1.x,a1.y,a1.z,a1.w};
    float loc = 0.f;
    #pragma unroll
    for (int i = 0; i < 8; ++i) {
        float a = v[i] * inv;
        loc += a * __logf(a + 1e-10f);
    }
    #pragma unroll
    for (int o = 16; o; o >>= 1) loc += __shfl_xor_sync(0xffffffffu, loc, o);
    __shared__ float red[8];
    if ((t & 31) == 0) red[t >> 5] = loc;
    __syncthreads();
    if (t == 0) {
        float tot = 0.f;
        #pragma unroll
        for (int i = 0; i < 8; ++i) tot += red[i];
        float e = -tot;
        float g = 1.0f / (1.0f + __expf(-(w1p[0]*e + bp[0])));
        if (e < 0.5f)       g = 0.f;
        else if (e > 2.0f)  g = fminf(g, 0.8f);
        g_gate[bs] = g;
    }
}

// ============================================================
// fused: q-proj + scores + softmax(+gate fold) + aux GEMM + fuse
// 128 CTAs x 256 threads; 32 rows/CTA. All FMAs packed f32x2.
// ============================================================
#define RK   32        // rows per CTA
#define KC   256       // k-chunk for q-proj
#define HPAD 260
#define QPAD 68
#define KPAD 68

#define OFF_HID 0
#define OFF_W   (RK*HPAD)                 // 8320
#define OFF_Q   (OFF_W + KC*DD)           // 24704
#define OFF_K   (OFF_Q + RK*QPAD)         // 26880
#define OFF_SC  (OFF_K + NSL*KPAD)        // 33680
#define OFF_AT  (OFF_SC + RK*NSL)         // 36880 (16B aligned)
#define SMEM_FLOATS (OFF_AT + NSL*RK)     // 40080 floats = 160320 B

__global__ __launch_bounds__(256, 1)
void fused_kernel(const float* __restrict__ hidden,
                  const float* __restrict__ primary,
                  const float* __restrict__ keys,
                  const float* __restrict__ vals,
                  float* __restrict__ out)
{
    extern __shared__ float sm[];
    int t = threadIdx.x;
    int row0 = blockIdx.x * RK;
    int r  = t >> 3;       // 0..31
    int d8 = t & 7;        // 0..7  -> owns d = 4*d8..+3 and 4*d8+32..+35

    // ---------- phase A: q = hidden @ WqT ----------
    ull acc0 = 0, acc1 = 0, acc2 = 0, acc3 = 0;
    for (int k0 = 0; k0 < HH; k0 += KC) {
        #pragma unroll
        for (int i = 0; i < 8; ++i) {
            int idx = t + i*256;                 // 0..2047
            int rr = idx >> 6, c4 = idx & 63;
            float4 x = *(const float4*)(hidden + (size_t)(row0+rr)*HH + k0 + (c4<<2));
            *(float4*)(sm + OFF_HID + rr*HPAD + (c4<<2)) = x;
        }
        const float4* wg = (const float4*)(g_WqT + (size_t)k0*DD);
        #pragma unroll
        for (int i = 0; i < 16; ++i)
            ((float4*)(sm + OFF_W))[t + i*256] = wg[t + i*256];
        __syncthreads();

        const float* hr = sm + OFF_HID + r*HPAD;
        #pragma unroll 4
        for (int h = 0; h < KC; ++h) {
            float a = hr[h];
            ull aa = pk2(a, a);
            F4U w0, w1;
            w0.f = *(const float4*)(sm + OFF_W + h*DD + (d8<<2));
            w1.f = *(const float4*)(sm + OFF_W + h*DD + (d8<<2) + 32);
            fma2(acc0, w0.u[0], aa);
            fma2(acc1, w0.u[1], aa);
            fma2(acc2, w1.u[0], aa);
            fma2(acc3, w1.u[1], aa);
        }
        __syncthreads();
    }
    {
        float x, y;
        float* q = sm + OFF_Q + r*QPAD;
        upk2(acc0, x, y); q[(d8<<2)+0]  = x; q[(d8<<2)+1]  = y;
        upk2(acc1, x, y); q[(d8<<2)+2]  = x; q[(d8<<2)+3]  = y;
        upk2(acc2, x, y); q[(d8<<2)+32] = x; q[(d8<<2)+33] = y;
        upk2(acc3, x, y); q[(d8<<2)+34] = x; q[(d8<<2)+35] = y;
    }
    // keys + logrel into smem
    for (int idx = t; idx < NSL*DD; idx += 256) {
        int n = idx >> 6, d = idx & 63;
        sm[OFF_K + n*KPAD + d] = keys[idx];
    }
    if (t < NSL) sm[OFF_K + t*KPAD + DD] = g_logrel[t];
    __syncthreads();

    // ---------- phase B: scores ----------
    for (int p = t; p < RK*NSL; p += 256) {
        int rr = p / NSL, n = p - rr*NSL;
        const float4* q4 = (const float4*)(sm + OFF_Q + rr*QPAD);
        const float4* k4 = (const float4*)(sm + OFF_K + n*KPAD);
        float acc = 0.f;
        #pragma unroll
        for (int i = 0; i < 16; ++i) {
            float4 a = q4[i], b = k4[i];
            acc += a.x*b.x + a.y*b.y + a.z*b.z + a.w*b.w;
        }
        sm[OFF_SC + rr*NSL + n] = 0.125f*acc + sm[OFF_K + n*KPAD + DD];
    }
    __syncthreads();

    // ---------- phase C: softmax per row, fold gate, pack row-pairs ----------
    {
        int w = t >> 5, lane = t & 31;
        ull* attn2 = (ull*)(sm + OFF_AT);
        #pragma unroll
        for (int j = 0; j < 2; ++j) {
            int rp = w*2 + j;
            int r0 = rp*2, r1 = r0 + 1;
            float e0[4], e1[4];
            float m0 = -1e30f, m1 = -1e30f;
            #pragma unroll
            for (int k = 0; k < 4; ++k) {
                int n = lane + k*32;
                float s0 = (n < NSL) ? sm[OFF_SC + r0*NSL + n] : -1e30f;
                float s1 = (n < NSL) ? sm[OFF_SC + r1*NSL + n] : -1e30f;
                e0[k] = s0; e1[k] = s1;
                m0 = fmaxf(m0, s0); m1 = fmaxf(m1, s1);
            }
            #pragma unroll
            for (int o = 16; o; o >>= 1) {
                m0 = fmaxf(m0, __shfl_xor_sync(0xffffffffu, m0, o));
                m1 = fmaxf(m1, __shfl_xor_sync(0xffffffffu, m1, o));
            }
            float sum0 = 0.f, sum1 = 0.f;
            #pragma unroll
            for (int k = 0; k < 4; ++k) {
                int n = lane + k*32;
                float x0 = (n < NSL) ? __expf(e0[k] - m0) : 0.f;
                float x1 = (n < NSL) ? __expf(e1[k] - m1) : 0.f;
                e0[k] = x0; e1[k] = x1;
                sum0 += x0; sum1 += x1;
            }
            #pragma unroll
            for (int o = 16; o; o >>= 1) {
                sum0 += __shfl_xor_sync(0xffffffffu, sum0, o);
                sum1 += __shfl_xor_sync(0xffffffffu, sum1, o);
            }
            float inv0 = g_gate[row0 + r0] / sum0;   // fold gate here
            float inv1 = g_gate[row0 + r1] / sum1;
            #pragma unroll
            for (int k = 0; k < 4; ++k) {
                int n = lane + k*32;
                if (n < NSL) attn2[n*16 + rp] = pk2(e0[k]*inv0, e1[k]*inv1);
            }
        }
    }
    __syncthreads();

    // ---------- phase D: out = primary + (gate*attn) @ V ----------
    const ull* attn2 = (const ull*)(sm + OFF_AT);
    for (int c0 = 0; c0 < HH; c0 += 512) {
        int cA = c0 + t, cB = cA + 256;
        ull aA[16], aB[16];
        #pragma unroll
        for (int rp = 0; rp < 16; ++rp) {
            size_t rb = (size_t)(row0 + rp*2) * HH;
            aA[rp] = pk2(primary[rb + cA], primary[rb + HH + cA]);
            aB[rp] = pk2(primary[rb + cB], primary[rb + HH + cB]);
        }
        float vA = vals[cA], vB = vals[cB];     // n = 0 prefetch
        for (int n = 0; n < NSL; ++n) {
            int np = (n + 1 < NSL) ? n + 1 : n;
            float nvA = vals[(size_t)np*HH + cA];
            float nvB = vals[(size_t)np*HH + cB];
            ull vvA = pk2(vA, vA), vvB = pk2(vB, vB);
            const float4* arow = (const float4*)(attn2 + n*16);
            #pragma unroll
            for (int j = 0; j < 8; ++j) {
                F4U u; u.f = arow[j];            // LDS.128 broadcast
                fma2(aA[2*j],   u.u[0], vvA);
                fma2(aA[2*j+1], u.u[1], vvA);
                fma2(aB[2*j],   u.u[0], vvB);
                fma2(aB[2*j+1], u.u[1], vvB);
            }
            vA = nvA; vB = nvB;
        }
        #pragma unroll
        for (int rp = 0; rp < 16; ++rp) {
            float x, y;
            size_t rb = (size_t)(row0 + rp*2) * HH;
            upk2(aA[rp], x, y); out[rb + cA] = x; out[rb + HH + cA] = y;
            upk2(aB[rp], x, y); out[rb + cB] = x; out[rb + HH + cB] = y;
        }
    }
}

// ============================================================
extern "C" void kernel_launch(void* const* d_in, const int* in_sizes, int n_in,
                              void* d_out, int out_size)
{
    const float* hidden  = (const float*)d_in[0];  // [B,S,H]
    const float* primary = (const float*)d_in[1];  // [B,S,H]
    const float* paw     = (const float*)d_in[2];  // [B,NH,S,S]
    const float* rel     = (const float*)d_in[3];  // [NS]
    const float* Wq      = (const float*)d_in[4];  // [D,H]
    const float* keys    = (const float*)d_in[5];  // [NS,D]
    const float* vals    = (const float*)d_in[6];  // [NS,H]
    const float* gw1     = (const float*)d_in[7];  // scalar
    const float* gb      = (const float*)d_in[8];  // scalar
    float* out = (float*)d_out;

    cudaFuncSetAttribute(fused_kernel,
                         cudaFuncAttributeMaxDynamicSharedMemorySize,
                         SMEM_FLOATS * (int)sizeof(float));

    prep_kernel<<<(HH*DD + 255)/256, 256>>>(Wq, rel);
    entropy_kernel<<<BSR, 256>>>(paw, gw1, gb);
    fused_kernel<<<BSR/RK, 256, SMEM_FLOATS * sizeof(float)>>>(
        hidden, primary, keys, vals, out);
}